// round 7
// baseline (speedup 1.0000x reference)
#include <cuda_runtime.h>
#include <cuda_fp16.h>
#include <cstdint>

#define Bn 32
#define Tn 1500
#define En 512
#define An 512
#define Cn 10
#define KW 201
#define On 512
#define NA_CHUNKS 4
#define TC_CHUNKS 15

#define MT 128
#define NTC 128
#define BK 32
#define NCHUNK 16
#define MTILES 375
#define NTILES 4

#define PITCH 80
#define TILEB (128 * PITCH)        // 10240
#define OFF_AL TILEB
#define OFF_BH (2 * TILEB)
#define OFF_BL (3 * TILEB)
#define STAGE_BYTES (4 * TILEB)    // 40960
#define SMEM_GEMM (2 * STAGE_BYTES)

// ---------------- scratch ----------------
__device__ float g_decproj[Bn * An];
__device__ float g_attc[Bn * Tn * Cn];
__device__ float g_epart[Bn * Tn * NA_CHUNKS];
__device__ float g_cpart[Bn * TC_CHUNKS * En];
__device__ __half g_bhi[An * En];   // [n][k]
__device__ __half g_blo[An * En];

// ---------------- helpers ----------------
__device__ __forceinline__ uint32_t smem_u32(const void* p) {
    uint32_t a;
    asm("{ .reg .u64 t; cvta.to.shared.u64 t, %1; cvt.u32.u64 %0, t; }" : "=r"(a) : "l"(p));
    return a;
}

__device__ __forceinline__ void ldsm4(uint32_t& r0, uint32_t& r1, uint32_t& r2, uint32_t& r3,
                                      uint32_t addr) {
    asm volatile("ldmatrix.sync.aligned.m8n8.x4.shared.b16 {%0,%1,%2,%3}, [%4];"
                 : "=r"(r0), "=r"(r1), "=r"(r2), "=r"(r3) : "r"(addr));
}

__device__ __forceinline__ void mma16816(float* d, const uint32_t* a, const uint32_t* b) {
    asm volatile(
        "mma.sync.aligned.m16n8k16.row.col.f32.f16.f16.f32 "
        "{%0,%1,%2,%3}, {%4,%5,%6,%7}, {%8,%9}, {%0,%1,%2,%3};"
        : "+f"(d[0]), "+f"(d[1]), "+f"(d[2]), "+f"(d[3])
        : "r"(a[0]), "r"(a[1]), "r"(a[2]), "r"(a[3]), "r"(b[0]), "r"(b[1]));
}

__device__ __forceinline__ float fast_tanh(float x) {
    float e = __expf(2.0f * x);
    return 1.0f - 2.0f / (e + 1.0f);
}

__device__ __forceinline__ uint32_t h2u(__half2 h) {
    return *reinterpret_cast<uint32_t*>(&h);
}

// split 8 fp32 -> hi fp16x8 (one uint4) and lo fp16x8 (one uint4)
__device__ __forceinline__ void split8(const float4& A, const float4& B,
                                       uint4& hi, uint4& lo) {
    __half2 h0 = __floats2half2_rn(A.x, A.y);
    __half2 h1 = __floats2half2_rn(A.z, A.w);
    __half2 h2 = __floats2half2_rn(B.x, B.y);
    __half2 h3 = __floats2half2_rn(B.z, B.w);
    float2 f0 = __half22float2(h0), f1 = __half22float2(h1);
    float2 f2 = __half22float2(h2), f3 = __half22float2(h3);
    __half2 l0 = __floats2half2_rn(A.x - f0.x, A.y - f0.y);
    __half2 l1 = __floats2half2_rn(A.z - f1.x, A.w - f1.y);
    __half2 l2 = __floats2half2_rn(B.x - f2.x, B.y - f2.y);
    __half2 l3 = __floats2half2_rn(B.z - f3.x, B.w - f3.y);
    hi.x = h2u(h0); hi.y = h2u(h1); hi.z = h2u(h2); hi.w = h2u(h3);
    lo.x = h2u(l0); lo.y = h2u(l1); lo.z = h2u(l2); lo.w = h2u(l3);
}

// ---------------- K1: dec_proj ----------------
__global__ void k_dec(const float* __restrict__ dec_z,
                      const float* __restrict__ W_dec,
                      const float* __restrict__ b_enc) {
    int b = blockIdx.y;
    int a = blockIdx.x * 128 + threadIdx.x;
    __shared__ float z[512];
    for (int i = threadIdx.x; i < 512; i += 128) z[i] = dec_z[b * 512 + i];
    __syncthreads();
    float acc = b_enc[a];
#pragma unroll 8
    for (int k = 0; k < 512; k++)
        acc = fmaf(z[k], W_dec[(size_t)k * An + a], acc);
    g_decproj[b * An + a] = acc;
}

// ---------------- K2: location conv (sliding window) ----------------
__global__ void k_conv(const float* __restrict__ att_prev,
                       const float* __restrict__ conv_w) {
    int b = blockIdx.y;
    int t0 = blockIdx.x * 128;
    int tid = threadIdx.x;           // 160 threads: 16 t-groups x 10 c
    int tg = tid & 15, c = tid >> 4;
    int tb = tg * 8;
    __shared__ float cw[Cn * KW];
    __shared__ float xs[128 + 200];
    __shared__ float so[128 * Cn];
    for (int i = tid; i < Cn * KW; i += 160) cw[i] = conv_w[i];
    for (int i = tid; i < 128 + 200; i += 160) {
        int tt = t0 - 100 + i;
        xs[i] = (tt >= 0 && tt < Tn) ? att_prev[b * Tn + tt] : 0.0f;
    }
    __syncthreads();

    float acc[8] = {0, 0, 0, 0, 0, 0, 0, 0};
    float win[8];
#pragma unroll
    for (int j = 0; j < 8; j++) win[j] = xs[tb + j];
    const float* cwc = cw + c * KW;
#pragma unroll 8
    for (int h = 0; h < KW; h++) {
        float coef = cwc[h];
#pragma unroll
        for (int j = 0; j < 8; j++) acc[j] = fmaf(coef, win[j], acc[j]);
#pragma unroll
        for (int j = 0; j < 7; j++) win[j] = win[j + 1];
        win[7] = xs[tb + h + 8];
    }
#pragma unroll
    for (int j = 0; j < 8; j++) so[(tb + j) * Cn + c] = acc[j];
    __syncthreads();

    int nvalid = Tn - t0;
    if (nvalid > 128) nvalid = 128;
    float* dst = g_attc + ((size_t)b * Tn + t0) * Cn;
    for (int i = tid; i < nvalid * Cn; i += 160) dst[i] = so[i];
}

// ---------------- prep B: W_enc^T -> hi/lo fp16 [n][k] ----------------
__global__ void k_prep_b(const float* __restrict__ W_enc) {
    __shared__ float tile[32][33];
    int n0 = blockIdx.x * 32, k0 = blockIdx.y * 32;
    int tx = threadIdx.x, ty = threadIdx.y;  // 32 x 8
    for (int i = ty; i < 32; i += 8)
        tile[i][tx] = W_enc[(size_t)(k0 + i) * An + n0 + tx];
    __syncthreads();
    for (int i = ty; i < 32; i += 8) {
        float v = tile[tx][i];
        __half hi = __float2half_rn(v);
        __half lo = __float2half_rn(v - __half2float(hi));
        g_bhi[(size_t)(n0 + i) * En + k0 + tx] = hi;
        g_blo[(size_t)(n0 + i) * En + k0 + tx] = lo;
    }
}

// ---------------- K3: HMMA fp16-split GEMM, CTA 128x128, dbl-buffered ----
__global__ __launch_bounds__(256, 2) void k_gemm_e(
    const float* __restrict__ enc,
    const float* __restrict__ W_att,
    const float* __restrict__ gvec) {
    extern __shared__ char smem[];
    uint32_t sbase = smem_u32(smem);

    int tid = threadIdx.x;
    int wid = tid >> 5, lane = tid & 31;
    int wm = wid >> 1, wn = wid & 1;         // 4m x 2n warps, warp 32x64
    int ntile = blockIdx.x;                  // 0..3
    int mtile = blockIdx.y;                  // 0..374
    int row0 = mtile * MT;
    int n0 = ntile * NTC;

    float d[2][8][4];
#pragma unroll
    for (int mt = 0; mt < 2; mt++)
#pragma unroll
        for (int nt = 0; nt < 8; nt++)
#pragma unroll
            for (int r = 0; r < 4; r++) d[mt][nt][r] = 0.0f;

    // load/store maps: row lr (0..127), col half lc (0..1) of the 32-wide chunk
    int lr = tid >> 1, lc = tid & 1;
    const float* pa = enc + (size_t)(row0 + lr) * En + lc * 16;
    const __half* pbh = g_bhi + (size_t)(n0 + lr) * En + lc * 16;
    const __half* pbl = g_blo + (size_t)(n0 + lr) * En + lc * 16;
    uint32_t da = (uint32_t)(lr * PITCH + lc * 32);

    float4 a0, a1, a2, a3;
    uint4 rbh0, rbh1, rbl0, rbl1;
    auto load_regs = [&](int ck) {
        int ko = ck * BK;
        a0 = *(const float4*)(pa + ko);
        a1 = *(const float4*)(pa + ko + 4);
        a2 = *(const float4*)(pa + ko + 8);
        a3 = *(const float4*)(pa + ko + 12);
        rbh0 = *(const uint4*)(pbh + ko);
        rbh1 = *(const uint4*)(pbh + ko + 8);
        rbl0 = *(const uint4*)(pbl + ko);
        rbl1 = *(const uint4*)(pbl + ko + 8);
    };
    load_regs(0);

    uint32_t laneA = (uint32_t)((lane & 15) * PITCH + (lane >> 4) * 16);
    uint32_t laneB = (uint32_t)(((((lane >> 4) << 3) + (lane & 7))) * PITCH + ((lane >> 3) & 1) * 16);
    uint32_t warpA = (uint32_t)(wm * 32 * PITCH);
    uint32_t warpB = (uint32_t)(wn * 64 * PITCH);

#pragma unroll 1
    for (int ck = 0; ck < NCHUNK; ck++) {
        int s = ck & 1;
        char* stn = smem + s * STAGE_BYTES;
        {
            uint4 hi, lo;
            split8(a0, a1, hi, lo);
            *(uint4*)(stn + da) = hi;
            *(uint4*)(stn + OFF_AL + da) = lo;
            split8(a2, a3, hi, lo);
            *(uint4*)(stn + da + 16) = hi;
            *(uint4*)(stn + OFF_AL + da + 16) = lo;
            *(uint4*)(stn + OFF_BH + da) = rbh0;
            *(uint4*)(stn + OFF_BH + da + 16) = rbh1;
            *(uint4*)(stn + OFF_BL + da) = rbl0;
            *(uint4*)(stn + OFF_BL + da + 16) = rbl1;
        }
        if (ck + 1 < NCHUNK) load_regs(ck + 1);
        __syncthreads();

        uint32_t stc = sbase + s * STAGE_BYTES;
        uint32_t aHb = stc + warpA + laneA;
        uint32_t aLb = stc + OFF_AL + warpA + laneA;
        uint32_t bHb = stc + OFF_BH + warpB + laneB;
        uint32_t bLb = stc + OFF_BL + warpB + laneB;

#pragma unroll
        for (int kh = 0; kh < 2; kh++) {
            uint32_t ko = kh * 32;  // 16 halves
            uint32_t aH[2][4], aL[2][4];
#pragma unroll
            for (int mt = 0; mt < 2; mt++) {
                ldsm4(aH[mt][0], aH[mt][1], aH[mt][2], aH[mt][3],
                      aHb + mt * (16 * PITCH) + ko);
                ldsm4(aL[mt][0], aL[mt][1], aL[mt][2], aL[mt][3],
                      aLb + mt * (16 * PITCH) + ko);
            }
#pragma unroll
            for (int g = 0; g < 4; g++) {
                uint32_t bh[4], bl[4];
                ldsm4(bh[0], bh[1], bh[2], bh[3], bHb + g * (16 * PITCH) + ko);
                ldsm4(bl[0], bl[1], bl[2], bl[3], bLb + g * (16 * PITCH) + ko);
#pragma unroll
                for (int mt = 0; mt < 2; mt++)
#pragma unroll
                    for (int f = 0; f < 2; f++) {
                        mma16816(d[mt][2 * g + f], aH[mt], &bh[2 * f]);
                        mma16816(d[mt][2 * g + f], aH[mt], &bl[2 * f]);
                        mma16816(d[mt][2 * g + f], aL[mt], &bh[2 * f]);
                    }
            }
        }
        // no barrier here: next iteration writes the other stage; the next
        // __syncthreads (after its STS) orders reuse of this stage.
    }
    __syncthreads();

    // ---- epilogue (reuse smem) ----
    float* s_dec0 = (float*)smem;         // 128
    float* s_dec1 = s_dec0 + 128;         // 128
    float* s_gv   = s_dec1 + 128;         // 128
    float* s_wat  = s_gv + 128;           // [10][128]
    float* s_atc  = s_wat + Cn * 128;     // [128][10]
    float* s_e    = s_atc + 128 * Cn;     // [128][2]

    int b0 = row0 / Tn;
    int b1 = (row0 + MT - 1) / Tn;
    if (tid < 128) {
        s_dec0[tid] = g_decproj[b0 * An + n0 + tid];
        s_dec1[tid] = g_decproj[b1 * An + n0 + tid];
        s_gv[tid] = gvec[n0 + tid];
    }
    for (int i = tid; i < Cn * 128; i += 256)
        s_wat[i] = W_att[(i >> 7) * An + n0 + (i & 127)];
    for (int i = tid; i < 128 * Cn; i += 256) {
        int r = i / Cn, c = i % Cn;
        int grow = row0 + r;
        int b = grow / Tn, t = grow - b * Tn;
        s_atc[r * Cn + c] = g_attc[((size_t)b * Tn + t) * Cn + c];
    }
    __syncthreads();

    int gid = lane >> 2, tid2 = lane & 3;
#pragma unroll
    for (int mt = 0; mt < 2; mt++) {
        int r0l = wm * 32 + mt * 16 + gid;
        int r1l = r0l + 8;
        int gb0 = (row0 + r0l) / Tn;
        int gb1 = (row0 + r1l) / Tn;
        const float* dec0 = (gb0 == b0) ? s_dec0 : s_dec1;
        const float* dec1 = (gb1 == b0) ? s_dec0 : s_dec1;
        float s0 = 0.0f, s1 = 0.0f;
#pragma unroll
        for (int nt = 0; nt < 8; nt++) {
            int n = wn * 64 + nt * 8 + tid2 * 2;
#pragma unroll
            for (int j = 0; j < 2; j++) {
                int nn = n + j;
                float v0 = d[mt][nt][j] + dec0[nn];
                float v1 = d[mt][nt][2 + j] + dec1[nn];
#pragma unroll
                for (int c = 0; c < Cn; c++) {
                    float w = s_wat[c * 128 + nn];
                    v0 = fmaf(s_atc[r0l * Cn + c], w, v0);
                    v1 = fmaf(s_atc[r1l * Cn + c], w, v1);
                }
                s0 = fmaf(fast_tanh(v0), s_gv[nn], s0);
                s1 = fmaf(fast_tanh(v1), s_gv[nn], s1);
            }
        }
        s0 += __shfl_xor_sync(0xffffffffu, s0, 1);
        s0 += __shfl_xor_sync(0xffffffffu, s0, 2);
        s1 += __shfl_xor_sync(0xffffffffu, s1, 1);
        s1 += __shfl_xor_sync(0xffffffffu, s1, 2);
        if (tid2 == 0) {
            s_e[r0l * 2 + wn] = s0;
            s_e[r1l * 2 + wn] = s1;
        }
    }
    __syncthreads();
    if (tid < 128) {
        float e = s_e[tid * 2 + 0] + s_e[tid * 2 + 1];
        int grow = row0 + tid;
        int b = grow / Tn, t = grow - b * Tn;
        g_epart[((size_t)b * Tn + t) * NA_CHUNKS + ntile] = e;
    }
}

// ---------------- K4: softmax ----------------
__global__ void k_softmax(float* __restrict__ w_out) {
    int b = blockIdx.x, tid = threadIdx.x;
    __shared__ float es[Tn];
    __shared__ float red[512];
    for (int t = tid; t < Tn; t += 512) {
        const float* p = &g_epart[((size_t)b * Tn + t) * NA_CHUNKS];
        es[t] = 2.0f * (p[0] + p[1] + p[2] + p[3]);
    }
    __syncthreads();
    float mx = -1e30f;
    for (int t = tid; t < Tn; t += 512) mx = fmaxf(mx, es[t]);
    red[tid] = mx;
    __syncthreads();
    for (int s = 256; s > 0; s >>= 1) {
        if (tid < s) red[tid] = fmaxf(red[tid], red[tid + s]);
        __syncthreads();
    }
    mx = red[0];
    __syncthreads();
    float sum = 0.0f;
    for (int t = tid; t < Tn; t += 512) {
        float ex = __expf(es[t] - mx);
        es[t] = ex;
        sum += ex;
    }
    red[tid] = sum;
    __syncthreads();
    for (int s = 256; s > 0; s >>= 1) {
        if (tid < s) red[tid] += red[tid + s];
        __syncthreads();
    }
    float inv = 1.0f / red[0];
    for (int t = tid; t < Tn; t += 512) w_out[b * Tn + t] = es[t] * inv;
}

// ---------------- K5: context partials (float4) ----------------
__global__ void k_ctx(const float* __restrict__ enc,
                      const float* __restrict__ w) {
    int b = blockIdx.y, tc = blockIdx.x;
    int e = threadIdx.x * 4;
    const float* encb = enc + (size_t)b * Tn * En;
    const float* wb = w + b * Tn;
    int t0 = tc * 100;
    float4 acc = make_float4(0.f, 0.f, 0.f, 0.f);
#pragma unroll 4
    for (int t = t0; t < t0 + 100; t++) {
        float wt = wb[t];
        float4 v = *(const float4*)(encb + (size_t)t * En + e);
        acc.x = fmaf(wt, v.x, acc.x);
        acc.y = fmaf(wt, v.y, acc.y);
        acc.z = fmaf(wt, v.z, acc.z);
        acc.w = fmaf(wt, v.w, acc.w);
    }
    *(float4*)(&g_cpart[((size_t)b * TC_CHUNKS + tc) * En + e]) = acc;
}

// ---------------- K6: out_c ----------------
__global__ void k_out(const float* __restrict__ W_o,
                      const float* __restrict__ b_o,
                      float* __restrict__ out_c) {
    int b = blockIdx.y;
    int o = blockIdx.x * 128 + threadIdx.x;
    __shared__ float cs[En];
    for (int e = threadIdx.x; e < En; e += 128) {
        float s = 0.0f;
#pragma unroll
        for (int ch = 0; ch < TC_CHUNKS; ch++)
            s += g_cpart[((size_t)b * TC_CHUNKS + ch) * En + e];
        cs[e] = s;
    }
    __syncthreads();
    float acc = b_o[o];
#pragma unroll 8
    for (int e = 0; e < En; e++)
        acc = fmaf(cs[e], W_o[(size_t)e * On + o], acc);
    out_c[(size_t)b * On + o] = acc;
}

// ---------------- launch ----------------
extern "C" void kernel_launch(void* const* d_in, const int* in_sizes, int n_in,
                              void* d_out, int out_size) {
    const float* enc      = (const float*)d_in[0];
    const float* dec_z    = (const float*)d_in[2];
    const float* att_prev = (const float*)d_in[3];
    const float* W_enc    = (const float*)d_in[4];
    const float* b_enc    = (const float*)d_in[5];
    const float* W_dec    = (const float*)d_in[6];
    const float* W_att    = (const float*)d_in[7];
    const float* conv_w   = (const float*)d_in[8];
    const float* gvec     = (const float*)d_in[9];
    const float* W_o      = (const float*)d_in[10];
    const float* b_o      = (const float*)d_in[11];

    float* out   = (float*)d_out;
    float* out_c = out;            // [B, O]
    float* out_w = out + Bn * On;  // [B, T]

    cudaFuncSetAttribute(k_gemm_e, cudaFuncAttributeMaxDynamicSharedMemorySize, SMEM_GEMM);

    k_prep_b<<<dim3(16, 16), dim3(32, 8)>>>(W_enc);
    k_dec<<<dim3(4, Bn), 128>>>(dec_z, W_dec, b_enc);
    k_conv<<<dim3(12, Bn), 160>>>(att_prev, conv_w);
    k_gemm_e<<<dim3(NTILES, MTILES), 256, SMEM_GEMM>>>(enc, W_att, gvec);
    k_softmax<<<Bn, 512>>>(out_w);
    k_ctx<<<dim3(TC_CHUNKS, Bn), 128>>>(enc, out_w);
    k_out<<<dim3(On / 128, Bn), 128>>>(W_o, b_o, out_c);
}